// round 3
// baseline (speedup 1.0000x reference)
#include <cuda_runtime.h>
#include <math.h>

// ---------------- Problem constants ----------------
#define WE 300
#define TE 10
#define SL 24
#define NT1 6
#define UT 3
#define H_LSTM 75          // WE/4
#define H_GRU 77           // (WE+TE)/4
#define CLS 27
#define D_IN 7210          // SL*WE + TE
#define BATCH 256
#define NSEQ 4608          // BATCH*UT*NT1  (LSTM scan length)
#define LSTM_B 24          // LSTM "batch" (= SL), independent sequences
#define G4 300             // 4*H_LSTM (gate width)
#define G3 231             // 3*H_GRU
#define CTXF 310           // WE+TE

// ---------------- Scratch (static device globals; no runtime alloc) -------
__device__ float g_X[(long)NSEQ * LSTM_B * G4];   // 4608*24*300  (~132.7 MB)
__device__ float g_H[(long)NSEQ * LSTM_B * H_LSTM]; // 4608*24*75 (~33.2 MB)
__device__ float g_ctx[BATCH * CTXF];             // 256*310
__device__ float g_XG[BATCH * G3];                // 256*231
__device__ float g_seqlast[BATCH * H_GRU];        // 256*77

// ---------------- Activation helpers ----------------
__device__ __forceinline__ float sigmoidf_(float x) {
    return 1.0f / (1.0f + __expf(-x));
}
__device__ __forceinline__ float tanhf_(float x) {
    float e = __expf(-2.0f * fabsf(x));
    float t = (1.0f - e) / (1.0f + e);
    return copysignf(t, x);
}

// =====================================================================
// K1: X[r][n] = sum_d we_row(r)[d] * lstm_W[d][n] + lstm_b[n]
//     r = s*24+m ; we_row(r) = inputs + s*7210 + m*300
//     110592 x 300 x 300 fp32 GEMM, tiled 64x64x16, 4x4 register tiles.
// =====================================================================
__global__ __launch_bounds__(256) void gemm_x_kernel(
    const float* __restrict__ A,      // inputs
    const float* __restrict__ W,      // 300 x 300
    const float* __restrict__ bias)   // 300
{
    __shared__ float As[16][64 + 4];
    __shared__ float Bs[16][64 + 4];

    const int tid = threadIdx.x;
    const int tr = tid >> 4;          // 0..15
    const int tc = tid & 15;          // 0..15
    const int row0 = blockIdx.y * 64;
    const int col0 = blockIdx.x * 64;

    float acc[4][4];
#pragma unroll
    for (int i = 0; i < 4; i++)
#pragma unroll
        for (int j = 0; j < 4; j++) acc[i][j] = 0.0f;

    for (int k0 = 0; k0 < G4; k0 += 16) {
        // load A tile 64x16 (transposed into As[kk][r])
#pragma unroll
        for (int i = 0; i < 4; i++) {
            int idx = tid + i * 256;          // 0..1023
            int r = idx >> 4;
            int kk = idx & 15;
            int gk = k0 + kk;
            int grow = row0 + r;
            float v = 0.0f;
            if (gk < WE) {
                long off = (long)grow * 300 + (long)(grow / 24) * 10 + gk;
                v = A[off];
            }
            As[kk][r] = v;
        }
        // load B tile 16x64
#pragma unroll
        for (int i = 0; i < 4; i++) {
            int idx = tid + i * 256;
            int kk = idx >> 6;
            int cc = idx & 63;
            int gk = k0 + kk;
            int gc = col0 + cc;
            Bs[kk][cc] = (gk < WE && gc < G4) ? W[gk * G4 + gc] : 0.0f;
        }
        __syncthreads();

#pragma unroll
        for (int kk = 0; kk < 16; kk++) {
            float a[4], b[4];
#pragma unroll
            for (int i = 0; i < 4; i++) a[i] = As[kk][tr * 4 + i];
#pragma unroll
            for (int j = 0; j < 4; j++) b[j] = Bs[kk][tc * 4 + j];
#pragma unroll
            for (int i = 0; i < 4; i++)
#pragma unroll
                for (int j = 0; j < 4; j++) acc[i][j] += a[i] * b[j];
        }
        __syncthreads();
    }

#pragma unroll
    for (int i = 0; i < 4; i++) {
        int gr = row0 + tr * 4 + i;
#pragma unroll
        for (int j = 0; j < 4; j++) {
            int gc = col0 + tc * 4 + j;
            if (gc < G4) g_X[(long)gr * G4 + gc] = acc[i][j] + bias[gc];
        }
    }
}

// =====================================================================
// K2: LSTM recurrence. 24 blocks (one per independent sequence m).
//     Per step t: z[n] = X[t][m][n] + sum_k h[k]*U[k][n]
//     gates -> c,h update; h written to g_H[t][m][:].
//     U column cached in registers; h broadcast from smem via float4.
// =====================================================================
__global__ __launch_bounds__(320, 1) void lstm_kernel(
    const float* __restrict__ U)      // 75 x 300
{
    const int m = blockIdx.x;         // 0..23
    const int n = threadIdx.x;        // 0..319 (active < 300)

    __shared__ __align__(16) float h_s[80];
    __shared__ float act[G4];

    float Ureg[76];
    if (n < G4) {
#pragma unroll
        for (int k = 0; k < H_LSTM; k++) Ureg[k] = U[k * G4 + n];
        Ureg[75] = 0.0f;
    } else {
#pragma unroll
        for (int k = 0; k < 76; k++) Ureg[k] = 0.0f;
    }

    if (n < 80) h_s[n] = 0.0f;
    float c = 0.0f;                    // valid for n < 75
    __syncthreads();

    const float* xp = g_X + (long)m * G4 + n;   // step stride = 24*300
    float xv = (n < G4) ? xp[0] : 0.0f;

    for (int t = 0; t < NSEQ; t++) {
        float xnext = 0.0f;
        if (t + 1 < NSEQ && n < G4) xnext = xp[(long)(t + 1) * (LSTM_B * G4)];

        if (n < G4) {
            const float4* h4 = (const float4*)h_s;
            float z0 = xv, z1 = 0.0f, z2 = 0.0f, z3 = 0.0f;
#pragma unroll
            for (int q = 0; q < 19; q++) {
                float4 hv = h4[q];
                z0 += hv.x * Ureg[4 * q + 0];
                z1 += hv.y * Ureg[4 * q + 1];
                z2 += hv.z * Ureg[4 * q + 2];
                z3 += hv.w * Ureg[4 * q + 3];
            }
            float z = (z0 + z1) + (z2 + z3);
            float a;
            if (n >= 150 && n < 225) a = tanhf_(z);    // g gate
            else                     a = sigmoidf_(z); // i, f, o
            act[n] = a;
        }
        __syncthreads();

        if (n < H_LSTM) {
            float ai = act[n];
            float af = act[75 + n];
            float ag = act[150 + n];
            float ao = act[225 + n];
            c = af * c + ai * ag;
            float h = ao * tanhf_(c);
            h_s[n] = h;
            g_H[(long)t * (LSTM_B * H_LSTM) + m * H_LSTM + n] = h;
        }
        __syncthreads();
        xv = xnext;
    }
}

// =====================================================================
// K3: ctx[t][f] for u=2 only (the only GRU batch-row that matters).
//     mv[j] = sum_n A[n] * mean_m H[s(t,n)][m][j],  s = (t*3+2)*6+n
//     ctx[f<300] = (1000/1001)*(mv . Wtw[:,f] + sumA*btw[f]) + B0
//     ctx[300+q] = (1/1001)*sum_n A[n]*te[t,2,n,q] + B0
// =====================================================================
__global__ __launch_bounds__(128) void ctx_kernel(
    const float* __restrict__ Wtw,    // 75 x 300
    const float* __restrict__ btw,    // 300
    const float* __restrict__ Atw,    // 6
    const float* __restrict__ Btw,    // 1
    const float* __restrict__ in)     // inputs
{
    const int t = blockIdx.x;         // 0..255
    const int tid = threadIdx.x;

    __shared__ float mv[H_LSTM];

    if (tid < H_LSTM) {
        float acc = 0.0f;
#pragma unroll
        for (int nn = 0; nn < NT1; nn++) {
            int s = (t * 3 + 2) * 6 + nn;
            const float* hp = g_H + (long)s * (LSTM_B * H_LSTM) + tid;
            float sm = 0.0f;
#pragma unroll
            for (int mm = 0; mm < LSTM_B; mm++) sm += hp[mm * H_LSTM];
            acc += Atw[nn] * sm;
        }
        mv[tid] = acc * (1.0f / 24.0f);
    }
    __syncthreads();

    float sumA = 0.0f;
#pragma unroll
    for (int nn = 0; nn < NT1; nn++) sumA += Atw[nn];
    const float B0 = Btw[0];
    const float c1 = 1000.0f / 1001.0f;

    for (int f = tid; f < WE; f += blockDim.x) {
        float acc = 0.0f;
#pragma unroll
        for (int j = 0; j < H_LSTM; j++) acc += mv[j] * Wtw[j * WE + f];
        g_ctx[t * CTXF + f] = c1 * (acc + sumA * btw[f]) + B0;
    }
    for (int q = tid; q < TE; q += blockDim.x) {
        float acc = 0.0f;
#pragma unroll
        for (int nn = 0; nn < NT1; nn++) {
            int s = (t * 3 + 2) * 6 + nn;
            acc += Atw[nn] * in[(long)s * D_IN + SL * WE + q];
        }
        g_ctx[t * CTXF + WE + q] = acc * (1.0f / 1001.0f) + B0;
    }
}

// =====================================================================
// K4: XG[t][n] = ctx[t] . gru_W[:,n] + gru_b[0][n]
// =====================================================================
__global__ __launch_bounds__(256) void xg_kernel(
    const float* __restrict__ gruW,   // 310 x 231
    const float* __restrict__ grub)   // 2 x 231
{
    const int t = blockIdx.x;
    const int tid = threadIdx.x;
    __shared__ float xs[CTXF];
    for (int i = tid; i < CTXF; i += blockDim.x) xs[i] = g_ctx[t * CTXF + i];
    __syncthreads();
    for (int nn = tid; nn < G3; nn += blockDim.x) {
        float acc = grub[nn];
        for (int k = 0; k < CTXF; k++) acc += xs[k] * gruW[k * G3 + nn];
        g_XG[t * G3 + nn] = acc;
    }
}

// =====================================================================
// K5: GRU recurrence, single block, single sequence (u=2), 256 steps.
//     rg[n] = h . gruU[:,n] + b1[n]; gate math per H_GRU lane.
// =====================================================================
__global__ __launch_bounds__(256, 1) void gru_kernel(
    const float* __restrict__ gruU,   // 77 x 231
    const float* __restrict__ grub)   // 2 x 231
{
    const int n = threadIdx.x;        // 0..255 (active < 231)

    __shared__ __align__(16) float h_s[80];
    __shared__ float rg_s[G3];

    float Ureg[80];
    float b1n = 0.0f;
    if (n < G3) {
#pragma unroll
        for (int k = 0; k < H_GRU; k++) Ureg[k] = gruU[k * G3 + n];
#pragma unroll
        for (int k = H_GRU; k < 80; k++) Ureg[k] = 0.0f;
        b1n = grub[G3 + n];
    } else {
#pragma unroll
        for (int k = 0; k < 80; k++) Ureg[k] = 0.0f;
    }
    if (n < 80) h_s[n] = 0.0f;
    __syncthreads();

    for (int t = 0; t < BATCH; t++) {
        if (n < G3) {
            const float4* h4 = (const float4*)h_s;
            float z0 = b1n, z1 = 0.0f, z2 = 0.0f, z3 = 0.0f;
#pragma unroll
            for (int q = 0; q < 20; q++) {
                float4 hv = h4[q];
                z0 += hv.x * Ureg[4 * q + 0];
                z1 += hv.y * Ureg[4 * q + 1];
                z2 += hv.z * Ureg[4 * q + 2];
                z3 += hv.w * Ureg[4 * q + 3];
            }
            rg_s[n] = (z0 + z1) + (z2 + z3);
        }
        __syncthreads();

        if (n < H_GRU) {
            float xz = g_XG[t * G3 + n];
            float xr = g_XG[t * G3 + H_GRU + n];
            float xh = g_XG[t * G3 + 2 * H_GRU + n];
            float z = sigmoidf_(xz + rg_s[n]);
            float r = sigmoidf_(xr + rg_s[H_GRU + n]);
            float hh = tanhf_(xh + r * rg_s[2 * H_GRU + n]);
            float hold = h_s[n];
            float h = z * hold + (1.0f - z) * hh;
            h_s[n] = h;
            g_seqlast[t * H_GRU + n] = h;
        }
        __syncthreads();
    }
}

// =====================================================================
// K6: logits = seqlast @ lin_W + lin_b; softmax per row. 32 threads/row.
// =====================================================================
__global__ __launch_bounds__(32) void out_kernel(
    const float* __restrict__ linW,   // 77 x 27
    const float* __restrict__ linb,   // 27
    float* __restrict__ out)          // 256 x 27
{
    const int t = blockIdx.x;
    const int c = threadIdx.x;        // 0..31 (active < 27)

    float logit = 0.0f;
    if (c < CLS) {
        logit = linb[c];
        const float* hp = g_seqlast + t * H_GRU;
#pragma unroll
        for (int k = 0; k < H_GRU; k++) logit += hp[k] * linW[k * CLS + c];
    }

    float x = (c < CLS) ? logit : -3.4e38f;
    float mx = x;
#pragma unroll
    for (int off = 16; off > 0; off >>= 1)
        mx = fmaxf(mx, __shfl_xor_sync(0xffffffffu, mx, off));
    float e = (c < CLS) ? __expf(logit - mx) : 0.0f;
    float s = e;
#pragma unroll
    for (int off = 16; off > 0; off >>= 1)
        s += __shfl_xor_sync(0xffffffffu, s, off);
    if (c < CLS) out[t * CLS + c] = e / s;
}

// =====================================================================
extern "C" void kernel_launch(void* const* d_in, const int* in_sizes, int n_in,
                              void* d_out, int out_size)
{
    (void)in_sizes; (void)n_in; (void)out_size;
    const float* inputs   = (const float*)d_in[0];
    const float* lstm_W   = (const float*)d_in[1];
    const float* lstm_U   = (const float*)d_in[2];
    const float* lstm_b   = (const float*)d_in[3];
    const float* lin_tw_W = (const float*)d_in[4];
    const float* lin_tw_b = (const float*)d_in[5];
    const float* A_tweets = (const float*)d_in[6];
    const float* B_tweets = (const float*)d_in[7];
    const float* gru_W    = (const float*)d_in[8];
    const float* gru_U    = (const float*)d_in[9];
    const float* gru_b    = (const float*)d_in[10];
    const float* lin_W    = (const float*)d_in[11];
    const float* lin_b    = (const float*)d_in[12];
    float* out = (float*)d_out;

    gemm_x_kernel<<<dim3(5, 1728), 256>>>(inputs, lstm_W, lstm_b);
    lstm_kernel<<<24, 320>>>(lstm_U);
    ctx_kernel<<<256, 128>>>(lin_tw_W, lin_tw_b, A_tweets, B_tweets, inputs);
    xg_kernel<<<256, 256>>>(gru_W, gru_b);
    gru_kernel<<<1, 256>>>(gru_U, gru_b);
    out_kernel<<<256, 32>>>(lin_W, lin_b, out);
}

// round 4
// speedup vs baseline: 1.0016x; 1.0016x over previous
#include <cuda_runtime.h>
#include <math.h>

// ---------------- Problem constants ----------------
#define WE 300
#define TE 10
#define SL 24
#define NT1 6
#define UT 3
#define H_LSTM 75          // WE/4
#define H_GRU 77           // (WE+TE)/4
#define CLS 27
#define D_IN 7210          // SL*WE + TE
#define BATCH 256
#define NSEQ 4608          // BATCH*UT*NT1  (LSTM scan length)
#define LSTM_B 24          // LSTM "batch" (= SL), independent sequences
#define G4 300             // 4*H_LSTM (gate width)
#define G3 231             // 3*H_GRU
#define CTXF 310           // WE+TE

// ---------------- Scratch (static device globals; no runtime alloc) -------
__device__ float g_X[(long)NSEQ * LSTM_B * G4];   // 4608*24*300  (~132.7 MB)
__device__ float g_H[(long)NSEQ * LSTM_B * H_LSTM]; // 4608*24*75 (~33.2 MB)
__device__ float g_ctx[BATCH * CTXF];             // 256*310
__device__ float g_XG[BATCH * G3];                // 256*231
__device__ float g_seqlast[BATCH * H_GRU];        // 256*77

// ---------------- Activation helpers ----------------
__device__ __forceinline__ float sigmoidf_(float x) {
    return 1.0f / (1.0f + __expf(-x));
}
__device__ __forceinline__ float tanhf_(float x) {
    float e = __expf(-2.0f * fabsf(x));
    float t = (1.0f - e) / (1.0f + e);
    return copysignf(t, x);
}

// =====================================================================
// K1: X[r][n] = sum_d we_row(r)[d] * lstm_W[d][n] + lstm_b[n]
//     r = s*24+m ; we_row(r) = inputs + s*7210 + m*300
//     110592 x 300 x 300 fp32 GEMM, tiled 64x64x16, 4x4 register tiles.
// =====================================================================
__global__ __launch_bounds__(256) void gemm_x_kernel(
    const float* __restrict__ A,      // inputs
    const float* __restrict__ W,      // 300 x 300
    const float* __restrict__ bias)   // 300
{
    __shared__ float As[16][64 + 4];
    __shared__ float Bs[16][64 + 4];

    const int tid = threadIdx.x;
    const int tr = tid >> 4;          // 0..15
    const int tc = tid & 15;          // 0..15
    const int row0 = blockIdx.y * 64;
    const int col0 = blockIdx.x * 64;

    float acc[4][4];
#pragma unroll
    for (int i = 0; i < 4; i++)
#pragma unroll
        for (int j = 0; j < 4; j++) acc[i][j] = 0.0f;

    for (int k0 = 0; k0 < G4; k0 += 16) {
        // load A tile 64x16 (transposed into As[kk][r])
#pragma unroll
        for (int i = 0; i < 4; i++) {
            int idx = tid + i * 256;          // 0..1023
            int r = idx >> 4;
            int kk = idx & 15;
            int gk = k0 + kk;
            int grow = row0 + r;
            float v = 0.0f;
            if (gk < WE) {
                long off = (long)grow * 300 + (long)(grow / 24) * 10 + gk;
                v = A[off];
            }
            As[kk][r] = v;
        }
        // load B tile 16x64
#pragma unroll
        for (int i = 0; i < 4; i++) {
            int idx = tid + i * 256;
            int kk = idx >> 6;
            int cc = idx & 63;
            int gk = k0 + kk;
            int gc = col0 + cc;
            Bs[kk][cc] = (gk < WE && gc < G4) ? W[gk * G4 + gc] : 0.0f;
        }
        __syncthreads();

#pragma unroll
        for (int kk = 0; kk < 16; kk++) {
            float a[4], b[4];
#pragma unroll
            for (int i = 0; i < 4; i++) a[i] = As[kk][tr * 4 + i];
#pragma unroll
            for (int j = 0; j < 4; j++) b[j] = Bs[kk][tc * 4 + j];
#pragma unroll
            for (int i = 0; i < 4; i++)
#pragma unroll
                for (int j = 0; j < 4; j++) acc[i][j] += a[i] * b[j];
        }
        __syncthreads();
    }

#pragma unroll
    for (int i = 0; i < 4; i++) {
        int gr = row0 + tr * 4 + i;
#pragma unroll
        for (int j = 0; j < 4; j++) {
            int gc = col0 + tc * 4 + j;
            if (gc < G4) g_X[(long)gr * G4 + gc] = acc[i][j] + bias[gc];
        }
    }
}

// =====================================================================
// K2: LSTM recurrence. 24 blocks (one per independent sequence m).
//     Per step t: z[n] = X[t][m][n] + sum_k h[k]*U[k][n]
//     gates -> c,h update; h written to g_H[t][m][:].
//     U column cached in registers; h broadcast from smem via float4.
// =====================================================================
__global__ __launch_bounds__(320, 1) void lstm_kernel(
    const float* __restrict__ U)      // 75 x 300
{
    const int m = blockIdx.x;         // 0..23
    const int n = threadIdx.x;        // 0..319 (active < 300)

    __shared__ __align__(16) float h_s[80];
    __shared__ float act[G4];

    float Ureg[76];
    if (n < G4) {
#pragma unroll
        for (int k = 0; k < H_LSTM; k++) Ureg[k] = U[k * G4 + n];
        Ureg[75] = 0.0f;
    } else {
#pragma unroll
        for (int k = 0; k < 76; k++) Ureg[k] = 0.0f;
    }

    if (n < 80) h_s[n] = 0.0f;
    float c = 0.0f;                    // valid for n < 75
    __syncthreads();

    const float* xp = g_X + (long)m * G4 + n;   // step stride = 24*300
    float xv = (n < G4) ? xp[0] : 0.0f;

    for (int t = 0; t < NSEQ; t++) {
        float xnext = 0.0f;
        if (t + 1 < NSEQ && n < G4) xnext = xp[(long)(t + 1) * (LSTM_B * G4)];

        if (n < G4) {
            const float4* h4 = (const float4*)h_s;
            float z0 = xv, z1 = 0.0f, z2 = 0.0f, z3 = 0.0f;
#pragma unroll
            for (int q = 0; q < 19; q++) {
                float4 hv = h4[q];
                z0 += hv.x * Ureg[4 * q + 0];
                z1 += hv.y * Ureg[4 * q + 1];
                z2 += hv.z * Ureg[4 * q + 2];
                z3 += hv.w * Ureg[4 * q + 3];
            }
            float z = (z0 + z1) + (z2 + z3);
            float a;
            if (n >= 150 && n < 225) a = tanhf_(z);    // g gate
            else                     a = sigmoidf_(z); // i, f, o
            act[n] = a;
        }
        __syncthreads();

        if (n < H_LSTM) {
            float ai = act[n];
            float af = act[75 + n];
            float ag = act[150 + n];
            float ao = act[225 + n];
            c = af * c + ai * ag;
            float h = ao * tanhf_(c);
            h_s[n] = h;
            g_H[(long)t * (LSTM_B * H_LSTM) + m * H_LSTM + n] = h;
        }
        __syncthreads();
        xv = xnext;
    }
}

// =====================================================================
// K3: ctx[t][f] for u=2 only (the only GRU batch-row that matters).
//     mv[j] = sum_n A[n] * mean_m H[s(t,n)][m][j],  s = (t*3+2)*6+n
//     ctx[f<300] = (1000/1001)*(mv . Wtw[:,f] + sumA*btw[f]) + B0
//     ctx[300+q] = (1/1001)*sum_n A[n]*te[t,2,n,q] + B0
// =====================================================================
__global__ __launch_bounds__(128) void ctx_kernel(
    const float* __restrict__ Wtw,    // 75 x 300
    const float* __restrict__ btw,    // 300
    const float* __restrict__ Atw,    // 6
    const float* __restrict__ Btw,    // 1
    const float* __restrict__ in)     // inputs
{
    const int t = blockIdx.x;         // 0..255
    const int tid = threadIdx.x;

    __shared__ float mv[H_LSTM];

    if (tid < H_LSTM) {
        float acc = 0.0f;
#pragma unroll
        for (int nn = 0; nn < NT1; nn++) {
            int s = (t * 3 + 2) * 6 + nn;
            const float* hp = g_H + (long)s * (LSTM_B * H_LSTM) + tid;
            float sm = 0.0f;
#pragma unroll
            for (int mm = 0; mm < LSTM_B; mm++) sm += hp[mm * H_LSTM];
            acc += Atw[nn] * sm;
        }
        mv[tid] = acc * (1.0f / 24.0f);
    }
    __syncthreads();

    float sumA = 0.0f;
#pragma unroll
    for (int nn = 0; nn < NT1; nn++) sumA += Atw[nn];
    const float B0 = Btw[0];
    const float c1 = 1000.0f / 1001.0f;

    for (int f = tid; f < WE; f += blockDim.x) {
        float acc = 0.0f;
#pragma unroll
        for (int j = 0; j < H_LSTM; j++) acc += mv[j] * Wtw[j * WE + f];
        g_ctx[t * CTXF + f] = c1 * (acc + sumA * btw[f]) + B0;
    }
    for (int q = tid; q < TE; q += blockDim.x) {
        float acc = 0.0f;
#pragma unroll
        for (int nn = 0; nn < NT1; nn++) {
            int s = (t * 3 + 2) * 6 + nn;
            acc += Atw[nn] * in[(long)s * D_IN + SL * WE + q];
        }
        g_ctx[t * CTXF + WE + q] = acc * (1.0f / 1001.0f) + B0;
    }
}

// =====================================================================
// K4: XG[t][n] = ctx[t] . gru_W[:,n] + gru_b[0][n]
// =====================================================================
__global__ __launch_bounds__(256) void xg_kernel(
    const float* __restrict__ gruW,   // 310 x 231
    const float* __restrict__ grub)   // 2 x 231
{
    const int t = blockIdx.x;
    const int tid = threadIdx.x;
    __shared__ float xs[CTXF];
    for (int i = tid; i < CTXF; i += blockDim.x) xs[i] = g_ctx[t * CTXF + i];
    __syncthreads();
    for (int nn = tid; nn < G3; nn += blockDim.x) {
        float acc = grub[nn];
        for (int k = 0; k < CTXF; k++) acc += xs[k] * gruW[k * G3 + nn];
        g_XG[t * G3 + nn] = acc;
    }
}

// =====================================================================
// K5: GRU recurrence, single block, single sequence (u=2), 256 steps.
//     rg[n] = h . gruU[:,n] + b1[n]; gate math per H_GRU lane.
// =====================================================================
__global__ __launch_bounds__(256, 1) void gru_kernel(
    const float* __restrict__ gruU,   // 77 x 231
    const float* __restrict__ grub)   // 2 x 231
{
    const int n = threadIdx.x;        // 0..255 (active < 231)

    __shared__ __align__(16) float h_s[80];
    __shared__ float rg_s[G3];

    float Ureg[80];
    float b1n = 0.0f;
    if (n < G3) {
#pragma unroll
        for (int k = 0; k < H_GRU; k++) Ureg[k] = gruU[k * G3 + n];
#pragma unroll
        for (int k = H_GRU; k < 80; k++) Ureg[k] = 0.0f;
        b1n = grub[G3 + n];
    } else {
#pragma unroll
        for (int k = 0; k < 80; k++) Ureg[k] = 0.0f;
    }
    if (n < 80) h_s[n] = 0.0f;
    __syncthreads();

    for (int t = 0; t < BATCH; t++) {
        if (n < G3) {
            const float4* h4 = (const float4*)h_s;
            float z0 = b1n, z1 = 0.0f, z2 = 0.0f, z3 = 0.0f;
#pragma unroll
            for (int q = 0; q < 20; q++) {
                float4 hv = h4[q];
                z0 += hv.x * Ureg[4 * q + 0];
                z1 += hv.y * Ureg[4 * q + 1];
                z2 += hv.z * Ureg[4 * q + 2];
                z3 += hv.w * Ureg[4 * q + 3];
            }
            rg_s[n] = (z0 + z1) + (z2 + z3);
        }
        __syncthreads();

        if (n < H_GRU) {
            float xz = g_XG[t * G3 + n];
            float xr = g_XG[t * G3 + H_GRU + n];
            float xh = g_XG[t * G3 + 2 * H_GRU + n];
            float z = sigmoidf_(xz + rg_s[n]);
            float r = sigmoidf_(xr + rg_s[H_GRU + n]);
            float hh = tanhf_(xh + r * rg_s[2 * H_GRU + n]);
            float hold = h_s[n];
            float h = z * hold + (1.0f - z) * hh;
            h_s[n] = h;
            g_seqlast[t * H_GRU + n] = h;
        }
        __syncthreads();
    }
}

// =====================================================================
// K6: logits = seqlast @ lin_W + lin_b; softmax per row. 32 threads/row.
// =====================================================================
__global__ __launch_bounds__(32) void out_kernel(
    const float* __restrict__ linW,   // 77 x 27
    const float* __restrict__ linb,   // 27
    float* __restrict__ out)          // 256 x 27
{
    const int t = blockIdx.x;
    const int c = threadIdx.x;        // 0..31 (active < 27)

    float logit = 0.0f;
    if (c < CLS) {
        logit = linb[c];
        const float* hp = g_seqlast + t * H_GRU;
#pragma unroll
        for (int k = 0; k < H_GRU; k++) logit += hp[k] * linW[k * CLS + c];
    }

    float x = (c < CLS) ? logit : -3.4e38f;
    float mx = x;
#pragma unroll
    for (int off = 16; off > 0; off >>= 1)
        mx = fmaxf(mx, __shfl_xor_sync(0xffffffffu, mx, off));
    float e = (c < CLS) ? __expf(logit - mx) : 0.0f;
    float s = e;
#pragma unroll
    for (int off = 16; off > 0; off >>= 1)
        s += __shfl_xor_sync(0xffffffffu, s, off);
    if (c < CLS) out[t * CLS + c] = e / s;
}

// =====================================================================
extern "C" void kernel_launch(void* const* d_in, const int* in_sizes, int n_in,
                              void* d_out, int out_size)
{
    (void)in_sizes; (void)n_in; (void)out_size;
    const float* inputs   = (const float*)d_in[0];
    const float* lstm_W   = (const float*)d_in[1];
    const float* lstm_U   = (const float*)d_in[2];
    const float* lstm_b   = (const float*)d_in[3];
    const float* lin_tw_W = (const float*)d_in[4];
    const float* lin_tw_b = (const float*)d_in[5];
    const float* A_tweets = (const float*)d_in[6];
    const float* B_tweets = (const float*)d_in[7];
    const float* gru_W    = (const float*)d_in[8];
    const float* gru_U    = (const float*)d_in[9];
    const float* gru_b    = (const float*)d_in[10];
    const float* lin_W    = (const float*)d_in[11];
    const float* lin_b    = (const float*)d_in[12];
    float* out = (float*)d_out;

    gemm_x_kernel<<<dim3(5, 1728), 256>>>(inputs, lstm_W, lstm_b);
    lstm_kernel<<<24, 320>>>(lstm_U);
    ctx_kernel<<<256, 128>>>(lin_tw_W, lin_tw_b, A_tweets, B_tweets, inputs);
    xg_kernel<<<256, 256>>>(gru_W, gru_b);
    gru_kernel<<<1, 256>>>(gru_U, gru_b);
    out_kernel<<<256, 32>>>(lin_W, lin_b, out);
}